// round 2
// baseline (speedup 1.0000x reference)
#include <cuda_runtime.h>

// Problem constants
#define NB   2
#define LL   2048
#define DD   1024
#define HH   16
#define DH   64
#define NHTOT 32            // NB*HH
#define NROW 65536          // NHTOT*LL
#define QTILES 16           // LL/128

// (1/sqrt(D)) * log2(e): energies pre-scaled into base-2 domain
#define CSCALE 0.04508422002778f

// ---------------- scratch (static device allocations; no cudaMalloc) -------
static __device__ float g_q [NROW*DH];
static __device__ float g_k [NROW*DH];
static __device__ float g_v [NROW*DH];
static __device__ float g_ok[NROW*DH];
static __device__ float g_ov[NROW*DH];
static __device__ float g_de[NROW];       // diag energies (unscaled)
static __device__ float g_m [NROW];       // row max (base-2 domain)
static __device__ float g_s [NROW];       // row sum of 2^(e-m)
static __device__ float g_dp[NROW];       // diag probability
static __device__ float g_cs[NROW];       // column sums of off-diag probs
static __device__ float g_part[QTILES*NROW];  // per-qtile column partials
static __device__ float g_pre[NB*LL*DD];  // pre-fc activations

// fast exp2 for x <= 0 (clamped), ~1e-6 rel err, pure FFMA (avoids MUFU)
__device__ __forceinline__ float exp2c(float x) {
    x = fmaxf(x, -120.0f);
    float r = rintf(x);
    float f = x - r;                      // [-0.5, 0.5]
    float p = 0.0013333558f;
    p = fmaf(p, f, 0.0096181291f);
    p = fmaf(p, f, 0.0555041087f);
    p = fmaf(p, f, 0.2402265070f);
    p = fmaf(p, f, 0.6931471806f);
    p = fmaf(p, f, 1.0f);
    int ei = (int)r;
    float sc = __int_as_float((ei + 127) << 23);
    return p * sc;
}

// swizzled float4 slot in a [128 rows][16 float4] tile
__device__ __forceinline__ int slot(int row, int e4) {
    return (row << 4) + (e4 ^ (row & 15));
}

// ---------------- K1: head-wise projection x @ W^T, transpose to [nh][l][d]
__global__ void proj_kernel(const float* __restrict__ x,
                            const float* __restrict__ W, int sel) {
    __shared__ float Wt[DH][DH + 1];   // Wt[e][d] = W[d][e]
    __shared__ float xs[4][DH];
    int tid = threadIdx.x;
    for (int i = tid; i < DH * DH; i += 256) Wt[i & 63][i >> 6] = W[i];
    int r = tid >> 6, d = tid & 63;
    int row = blockIdx.x * 4 + r;          // row in (n, l, h) order
    xs[r][d] = x[row * DH + d];
    __syncthreads();
    float acc = 0.0f;
#pragma unroll
    for (int e = 0; e < DH; e++) acc = fmaf(xs[r][e], Wt[e][d], acc);
    int n = row >> 15;
    int l = (row >> 4) & (LL - 1);
    int h = row & 15;
    float* out = (sel == 0) ? g_q : (sel == 1) ? g_k : (sel == 2) ? g_v
               : (sel == 3) ? g_ok : g_ov;
    out[(((n << 4) + h) * LL + l) * DH + d] = acc;
}

// ---------------- K2a: diagonal energies q.k (one warp per row) ------------
__global__ void diag_kernel() {
    int g = blockIdx.x * 256 + threadIdx.x;
    int w = g >> 5, lane = g & 31;
    const float* qp = g_q + w * DH;
    const float* kp = g_k + w * DH;
    float a = qp[lane] * kp[lane] + qp[lane + 32] * kp[lane + 32];
#pragma unroll
    for (int o = 16; o; o >>= 1) a += __shfl_xor_sync(0xffffffffu, a, o);
    if (lane == 0) g_de[w] = a;
}

// shared 128x128 energy-tile compute (both passes use this, bitwise identical)
#define TILE_MMA(qs, os, acc, tx, ty)                                        \
    _Pragma("unroll")                                                        \
    for (int e4 = 0; e4 < 16; e4++) {                                        \
        float4 b[8];                                                         \
        _Pragma("unroll")                                                    \
        for (int j = 0; j < 8; j++) {                                        \
            int col = tx + (j << 4);                                         \
            b[j] = os[(col << 4) + (e4 ^ tx)];                               \
        }                                                                    \
        _Pragma("unroll")                                                    \
        for (int i = 0; i < 8; i++) {                                        \
            int rw = (ty << 3) + i;                                          \
            float4 a = qs[(rw << 4) + (e4 ^ (rw & 15))];                     \
            _Pragma("unroll")                                                \
            for (int j = 0; j < 8; j++) {                                    \
                acc[i][j] = fmaf(a.x, b[j].x, acc[i][j]);                    \
                acc[i][j] = fmaf(a.y, b[j].y, acc[i][j]);                    \
                acc[i][j] = fmaf(a.z, b[j].z, acc[i][j]);                    \
                acc[i][j] = fmaf(a.w, b[j].w, acc[i][j]);                    \
            }                                                                \
        }                                                                    \
    }

// ---------------- K2: pass 1 — row max & sum (online, base-2) --------------
__global__ void stats_kernel() {
    extern __shared__ float4 sh[];
    float4* qs = sh;            // 2048 float4 (32KB)
    float4* os = sh + 2048;     // 2048 float4 (32KB)
    int nh = blockIdx.y;
    int qt = (QTILES - 1) - blockIdx.x;    // heavy blocks first
    int q0 = qt << 7;
    const float* qb = g_q  + (size_t)nh * LL * DH;
    const float* ob = g_ok + (size_t)nh * LL * DH;
    int tid = threadIdx.x;
    for (int it = tid; it < 2048; it += 256) {
        int row = it >> 4, e4 = it & 15;
        float4 v = *(const float4*)(qb + (q0 + row) * DH + e4 * 4);
        v.x *= CSCALE; v.y *= CSCALE; v.z *= CSCALE; v.w *= CSCALE;
        qs[slot(row, e4)] = v;
    }
    int ty = tid >> 4, tx = tid & 15;
    float m[8], s[8], dsc[8];
#pragma unroll
    for (int i = 0; i < 8; i++) {
        m[i] = -3.0e38f; s[i] = 0.0f;
        dsc[i] = g_de[nh * LL + q0 + (ty << 3) + i] * CSCALE;
    }
    for (int l0 = 0; l0 <= q0; l0 += 128) {
        __syncthreads();
        for (int it = tid; it < 2048; it += 256) {
            int row = it >> 4, e4 = it & 15;
            os[slot(row, e4)] = *(const float4*)(ob + (l0 + row) * DH + e4 * 4);
        }
        __syncthreads();
        float acc[8][8];
#pragma unroll
        for (int i = 0; i < 8; i++)
#pragma unroll
            for (int j = 0; j < 8; j++) acc[i][j] = 0.0f;
        TILE_MMA(qs, os, acc, tx, ty)
        bool dt = (l0 == q0);
#pragma unroll
        for (int i = 0; i < 8; i++) {
            int gq = q0 + (ty << 3) + i;
            float ev[8];
            float tm = -3.0e38f;
#pragma unroll
            for (int j = 0; j < 8; j++) {
                float e = acc[i][j];
                if (dt) {
                    int gl = l0 + tx + (j << 4);
                    if (gl > gq) e = -3.0e38f;
                    else if (gl == gq) e = dsc[i];
                }
                ev[j] = e;
                tm = fmaxf(tm, e);
            }
            float mn = fmaxf(m[i], tm);
            float ss = s[i] * exp2c(m[i] - mn);
#pragma unroll
            for (int j = 0; j < 8; j++) ss += exp2c(ev[j] - mn);
            m[i] = mn; s[i] = ss;
        }
    }
    // merge (m,s) across tx = lane groups of 16
#pragma unroll
    for (int i = 0; i < 8; i++) {
        float mi = m[i], si = s[i];
#pragma unroll
        for (int o = 8; o; o >>= 1) {
            float mo = __shfl_xor_sync(0xffffffffu, mi, o);
            float so = __shfl_xor_sync(0xffffffffu, si, o);
            float mn = fmaxf(mi, mo);
            si = si * exp2c(mi - mn) + so * exp2c(mo - mn);
            mi = mn;
        }
        if (tx == 0) {
            int row = nh * LL + q0 + (ty << 3) + i;
            g_m[row] = mi; g_s[row] = si;
        }
    }
}

// ---------------- K3: pass 2 — diag probs + deterministic column partials --
__global__ void colsum_kernel() {
    extern __shared__ float4 sh[];
    float4* qs = sh;
    float4* os = sh + 2048;
    float* sred = (float*)(sh + 4096);   // 16*128 floats
    int nh = blockIdx.y;
    int qt = (QTILES - 1) - blockIdx.x;
    int q0 = qt << 7;
    const float* qb = g_q  + (size_t)nh * LL * DH;
    const float* ob = g_ok + (size_t)nh * LL * DH;
    int tid = threadIdx.x;
    for (int it = tid; it < 2048; it += 256) {
        int row = it >> 4, e4 = it & 15;
        float4 v = *(const float4*)(qb + (q0 + row) * DH + e4 * 4);
        v.x *= CSCALE; v.y *= CSCALE; v.z *= CSCALE; v.w *= CSCALE;
        qs[slot(row, e4)] = v;
    }
    int ty = tid >> 4, tx = tid & 15;
    float rm[8], ri[8], dsc[8];
#pragma unroll
    for (int i = 0; i < 8; i++) {
        int row = nh * LL + q0 + (ty << 3) + i;
        rm[i] = g_m[row];
        ri[i] = 1.0f / g_s[row];
        dsc[i] = g_de[row] * CSCALE;
    }
    for (int l0 = 0; l0 <= q0; l0 += 128) {
        __syncthreads();
        for (int it = tid; it < 2048; it += 256) {
            int row = it >> 4, e4 = it & 15;
            os[slot(row, e4)] = *(const float4*)(ob + (l0 + row) * DH + e4 * 4);
        }
        __syncthreads();
        float acc[8][8];
#pragma unroll
        for (int i = 0; i < 8; i++)
#pragma unroll
            for (int j = 0; j < 8; j++) acc[i][j] = 0.0f;
        TILE_MMA(qs, os, acc, tx, ty)
        bool dt = (l0 == q0);
        float cp[8];
#pragma unroll
        for (int j = 0; j < 8; j++) cp[j] = 0.0f;
#pragma unroll
        for (int i = 0; i < 8; i++) {
            int gq = q0 + (ty << 3) + i;
#pragma unroll
            for (int j = 0; j < 8; j++) {
                float e = acc[i][j];
                if (dt) {
                    int gl = l0 + tx + (j << 4);
                    if (gl > gq) e = -3.0e38f;
                    else if (gl == gq) {
                        g_dp[nh * LL + gq] = exp2c(dsc[i] - rm[i]) * ri[i];
                        e = -3.0e38f;   // diagonal excluded from colsum
                    }
                }
                cp[j] += exp2c(e - rm[i]) * ri[i];
            }
        }
#pragma unroll
        for (int j = 0; j < 8; j++) sred[ty * 128 + tx + (j << 4)] = cp[j];
        __syncthreads();
        if (tid < 128) {
            float sum = 0.0f;
#pragma unroll
            for (int t = 0; t < 16; t++) sum += sred[t * 128 + tid];
            g_part[(qt * NHTOT + nh) * LL + l0 + tid] = sum;
        }
    }
}

// ---------------- K3b: reduce per-qtile partials into column sums ----------
__global__ void reduce_kernel() {
    int idx = blockIdx.x * 256 + threadIdx.x;       // < NROW
    int l = idx & (LL - 1);
    int nh = idx >> 11;
    float sum = 0.0f;
    for (int qt = l >> 7; qt < QTILES; qt++)
        sum += g_part[(qt * NHTOT + nh) * LL + l];
    g_cs[idx] = sum;
}

// ---------------- K4a: pre = diag*v + colsum*ov, back to [n][l][h*64+d] ----
__global__ void pre_kernel() {
    int idx = blockIdx.x * 256 + threadIdx.x;       // < NB*LL*DD
    int d = idx & 63;
    int h = (idx >> 6) & 15;
    int l = (idx >> 10) & (LL - 1);
    int n = idx >> 21;
    int r = ((n << 4) + h) * LL + l;
    int b = r * DH + d;
    g_pre[idx] = g_dp[r] * g_v[b] + g_cs[r] * g_ov[b];
}

// ---------------- K4b: out = pre @ fc_w^T + fc_b ---------------------------
__global__ __launch_bounds__(256, 2) void fc_kernel(
        const float* __restrict__ Wfc, const float* __restrict__ bias,
        float* __restrict__ out) {
    extern __shared__ float4 sh[];
    float4* As = sh;
    float4* Bs = sh + 2048;
    int mt = blockIdx.y, ot = blockIdx.x;
    int m0 = mt << 7, o0 = ot << 7;
    int tid = threadIdx.x;
    int ty = tid >> 4, tx = tid & 15;
    float acc[8][8];
#pragma unroll
    for (int i = 0; i < 8; i++)
#pragma unroll
        for (int j = 0; j < 8; j++) acc[i][j] = 0.0f;
    for (int k0 = 0; k0 < DD; k0 += 64) {
        __syncthreads();
        for (int it = tid; it < 2048; it += 256) {
            int row = it >> 4, e4 = it & 15;
            As[slot(row, e4)] =
                *(const float4*)(g_pre + (size_t)(m0 + row) * DD + k0 + e4 * 4);
            Bs[slot(row, e4)] =
                *(const float4*)(Wfc + (size_t)(o0 + row) * DD + k0 + e4 * 4);
        }
        __syncthreads();
        TILE_MMA(As, Bs, acc, tx, ty)
    }
#pragma unroll
    for (int i = 0; i < 8; i++) {
        int row = m0 + (ty << 3) + i;
#pragma unroll
        for (int j = 0; j < 8; j++) {
            int col = o0 + tx + (j << 4);
            out[(size_t)row * DD + col] = acc[i][j] + bias[col];
        }
    }
}

// ---------------- launch ----------------------------------------------------
extern "C" void kernel_launch(void* const* d_in, const int* in_sizes, int n_in,
                              void* d_out, int out_size) {
    const float* values = (const float*)d_in[0];
    const float* keys   = (const float*)d_in[1];
    const float* query  = (const float*)d_in[2];
    const float* ovals  = (const float*)d_in[3];
    const float* okeys  = (const float*)d_in[4];
    const float* Wv     = (const float*)d_in[5];
    const float* Wk     = (const float*)d_in[6];
    const float* Wq     = (const float*)d_in[7];
    const float* fcw    = (const float*)d_in[8];
    const float* fcb    = (const float*)d_in[9];
    float* out = (float*)d_out;

    cudaFuncSetAttribute(stats_kernel,
        cudaFuncAttributeMaxDynamicSharedMemorySize, 65536);
    cudaFuncSetAttribute(colsum_kernel,
        cudaFuncAttributeMaxDynamicSharedMemorySize, 73728);
    cudaFuncSetAttribute(fc_kernel,
        cudaFuncAttributeMaxDynamicSharedMemorySize, 65536);

    proj_kernel<<<16384, 256>>>(query, Wq, 0);
    proj_kernel<<<16384, 256>>>(keys,  Wk, 1);
    proj_kernel<<<16384, 256>>>(values, Wv, 2);
    proj_kernel<<<16384, 256>>>(okeys, Wk, 3);
    proj_kernel<<<16384, 256>>>(ovals, Wv, 4);
    diag_kernel<<<NROW / 8, 256>>>();
    stats_kernel<<<dim3(QTILES, NHTOT), 256, 65536>>>();
    colsum_kernel<<<dim3(QTILES, NHTOT), 256, 73728>>>();
    reduce_kernel<<<NROW / 256, 256>>>();
    pre_kernel<<<NB * LL * DD / 256, 256>>>();
    fc_kernel<<<dim3(DD / 128, NB * LL / 128), 256, 65536>>>(fcw, fcb, out);
}

// round 3
// speedup vs baseline: 1.4677x; 1.4677x over previous
#include <cuda_runtime.h>
#include <cuda_fp16.h>

// Problem constants
#define NB   2
#define LL   2048
#define DD   1024
#define HH   16
#define DH   64
#define NHTOT 32            // NB*HH
#define NROW 65536          // NHTOT*LL
#define QTILES 16           // LL/128

// (1/sqrt(D)) * log2(e): energies pre-scaled into base-2 domain
#define CSCALE 0.04508422002778f

// ---------------- scratch (static device allocations; no cudaMalloc) -------
static __device__ float  g_q [NROW*DH];
static __device__ float  g_k [NROW*DH];
static __device__ float  g_v [NROW*DH];
static __device__ float  g_ok[NROW*DH];
static __device__ float  g_ov[NROW*DH];
static __device__ float  g_de[NROW];        // diag energies (unscaled)
static __device__ float  g_rs[NROW];        // 1 / row softmax denom
static __device__ float  g_dp[NROW];        // diag probability
static __device__ float  g_cs[NROW];        // column sums of off-diag probs
static __device__ float  g_part[8*NROW];    // per-qslice column partials
static __device__ float  g_pre[NB*LL*DD];   // pre-fc activations
static __device__ __half g_p[(size_t)NHTOT*LL*LL];  // unnormalized probs 2^e

// fast exp2, pure FFMA (avoids MUFU), ~1e-7 rel err for |x| small
__device__ __forceinline__ float exp2c(float x) {
    x = fmaxf(x, -120.0f);
    float r = rintf(x);
    float f = x - r;                      // [-0.5, 0.5]
    float p = 0.0013333558f;
    p = fmaf(p, f, 0.0096181291f);
    p = fmaf(p, f, 0.0555041087f);
    p = fmaf(p, f, 0.2402265070f);
    p = fmaf(p, f, 0.6931471806f);
    p = fmaf(p, f, 1.0f);
    int ei = (int)r;
    float sc = __int_as_float((ei + 127) << 23);
    return p * sc;
}

// swizzled float4 slot in a [128 rows][16 float4] tile
__device__ __forceinline__ int slot(int row, int e4) {
    return (row << 4) + (e4 ^ (row & 15));
}

// ---------------- K1: head-wise projection x @ W^T  (register-tiled) -------
// 128 rows per block, 256 threads, each thread 8 rows x 4 cols.
__global__ __launch_bounds__(256) void proj2_kernel(
        const float* __restrict__ x, const float* __restrict__ W,
        float* __restrict__ out) {
    __shared__ __align__(16) float Wt[DH][68];    // Wt[e][d] = W[d][e]
    __shared__ __align__(16) float xst[DH][132];  // xst[e][row]
    int tid = threadIdx.x;
    for (int i = tid; i < DH * DH; i += 256) Wt[i & 63][i >> 6] = W[i];
    int r0 = blockIdx.x << 7;
    for (int i = tid; i < 2048; i += 256) {
        int row = i >> 4, e4 = i & 15;
        float4 v = *(const float4*)(x + (size_t)(r0 + row) * DH + (e4 << 2));
        xst[(e4 << 2) + 0][row] = v.x;
        xst[(e4 << 2) + 1][row] = v.y;
        xst[(e4 << 2) + 2][row] = v.z;
        xst[(e4 << 2) + 3][row] = v.w;
    }
    __syncthreads();
    int ty = tid >> 4, tx = tid & 15;
    int rr = ty << 3, cc = tx << 2;
    float acc[8][4];
#pragma unroll
    for (int i = 0; i < 8; i++)
#pragma unroll
        for (int j = 0; j < 4; j++) acc[i][j] = 0.0f;
#pragma unroll
    for (int e = 0; e < DH; e++) {
        float4 a0 = *(const float4*)&xst[e][rr];
        float4 a1 = *(const float4*)&xst[e][rr + 4];
        float4 b  = *(const float4*)&Wt[e][cc];
        float av[8] = {a0.x, a0.y, a0.z, a0.w, a1.x, a1.y, a1.z, a1.w};
#pragma unroll
        for (int i = 0; i < 8; i++) {
            acc[i][0] = fmaf(av[i], b.x, acc[i][0]);
            acc[i][1] = fmaf(av[i], b.y, acc[i][1]);
            acc[i][2] = fmaf(av[i], b.z, acc[i][2]);
            acc[i][3] = fmaf(av[i], b.w, acc[i][3]);
        }
    }
#pragma unroll
    for (int i = 0; i < 8; i++) {
        int row = r0 + rr + i;                 // (n, l, h) order
        int n = row >> 15;
        int l = (row >> 4) & (LL - 1);
        int h = row & 15;
        size_t orow = (size_t)((n << 4) + h) * LL + l;
        *(float4*)(out + orow * DH + cc) =
            make_float4(acc[i][0], acc[i][1], acc[i][2], acc[i][3]);
    }
}

// ---------------- K2a: diagonal energies q.k (one warp per row) ------------
__global__ void diag_kernel() {
    int g = blockIdx.x * 256 + threadIdx.x;
    int w = g >> 5, lane = g & 31;
    const float* qp = g_q + (size_t)w * DH;
    const float* kp = g_k + (size_t)w * DH;
    float a = qp[lane] * kp[lane] + qp[lane + 32] * kp[lane + 32];
#pragma unroll
    for (int o = 16; o; o >>= 1) a += __shfl_xor_sync(0xffffffffu, a, o);
    if (lane == 0) g_de[w] = a;
}

// shared 128x128 tile MMA (8x8 register tile per thread)
#define TILE_MMA(qs, os, acc, tx, ty)                                        \
    _Pragma("unroll")                                                        \
    for (int e4 = 0; e4 < 16; e4++) {                                        \
        float4 b[8];                                                         \
        _Pragma("unroll")                                                    \
        for (int j = 0; j < 8; j++) {                                        \
            int col = tx + (j << 4);                                         \
            b[j] = os[(col << 4) + (e4 ^ tx)];                               \
        }                                                                    \
        _Pragma("unroll")                                                    \
        for (int i = 0; i < 8; i++) {                                        \
            int rw = (ty << 3) + i;                                          \
            float4 a = qs[(rw << 4) + (e4 ^ (rw & 15))];                     \
            _Pragma("unroll")                                                \
            for (int j = 0; j < 8; j++) {                                    \
                acc[i][j] = fmaf(a.x, b[j].x, acc[i][j]);                    \
                acc[i][j] = fmaf(a.y, b[j].y, acc[i][j]);                    \
                acc[i][j] = fmaf(a.z, b[j].z, acc[i][j]);                    \
                acc[i][j] = fmaf(a.w, b[j].w, acc[i][j]);                    \
            }                                                                \
        }                                                                    \
    }

// ---------------- K2: single pass — probs to fp16 P + exact row sums -------
__global__ __launch_bounds__(256, 2) void qk_kernel() {
    extern __shared__ float4 sh[];
    float4* qs = sh;            // 32KB
    float4* os = sh + 2048;     // 32KB
    __half* ps = (__half*)(sh + 4096);   // 128x128 fp16 tile, 32KB
    int nh = blockIdx.y;
    int qt = (QTILES - 1) - blockIdx.x;  // heavy blocks first
    int q0 = qt << 7;
    const float* qb = g_q  + (size_t)nh * LL * DH;
    const float* ob = g_ok + (size_t)nh * LL * DH;
    __half* Pp = g_p + (size_t)nh * LL * LL;
    int tid = threadIdx.x;
    for (int it = tid; it < 2048; it += 256) {
        int row = it >> 4, e4 = it & 15;
        float4 v = *(const float4*)(qb + (size_t)(q0 + row) * DH + (e4 << 2));
        v.x *= CSCALE; v.y *= CSCALE; v.z *= CSCALE; v.w *= CSCALE;
        qs[slot(row, e4)] = v;
    }
    int ty = tid >> 4, tx = tid & 15;
    float s[8], dsc[8];
#pragma unroll
    for (int i = 0; i < 8; i++) {
        s[i] = 0.0f;
        dsc[i] = g_de[nh * LL + q0 + (ty << 3) + i] * CSCALE;
    }
    for (int l0 = 0; l0 <= q0; l0 += 128) {
        __syncthreads();
        for (int it = tid; it < 2048; it += 256) {
            int row = it >> 4, e4 = it & 15;
            os[slot(row, e4)] = *(const float4*)(ob + (size_t)(l0 + row) * DH + (e4 << 2));
        }
        __syncthreads();
        float acc[8][8];
#pragma unroll
        for (int i = 0; i < 8; i++)
#pragma unroll
            for (int j = 0; j < 8; j++) acc[i][j] = 0.0f;
        TILE_MMA(qs, os, acc, tx, ty)
        bool dt = (l0 == q0);
#pragma unroll
        for (int i = 0; i < 8; i++) {
            int gq = q0 + (ty << 3) + i;
#pragma unroll
            for (int j = 0; j < 8; j++) {
                int gl = l0 + tx + (j << 4);
                float u;
                if (dt && gl >= gq) u = 0.0f;   // causal mask + diag excluded
                else u = exp2c(acc[i][j]);
                s[i] += u;
                ps[((ty << 3) + i) * 128 + tx + (j << 4)] = __float2half_rn(u);
            }
        }
        __syncthreads();
        for (int it = tid; it < 2048; it += 256) {
            int row = it >> 4, c8 = (it & 15) << 3;
            *(float4*)(Pp + (size_t)(q0 + row) * LL + l0 + c8) =
                *(const float4*)(ps + row * 128 + c8);
        }
    }
    // reduce s across the 16 tx lanes; diag term (samp energy) added at end
#pragma unroll
    for (int i = 0; i < 8; i++) {
        float si = s[i];
#pragma unroll
        for (int o = 8; o; o >>= 1) si += __shfl_xor_sync(0xffffffffu, si, o);
        if (tx == 0) {
            float ud = exp2c(dsc[i]);
            float rinv = 1.0f / (si + ud);
            int row = nh * LL + q0 + (ty << 3) + i;
            g_rs[row] = rinv;
            g_dp[row] = ud * rinv;
        }
    }
}

// ---------------- K3: column partial sums over q-slices (mem-bound) --------
__global__ void colsum2_kernel() {
    int nh = blockIdx.y;
    int l0 = blockIdx.x << 7;              // 16 column tiles of 128
    int qz = blockIdx.z;                   // 4 q-chunks of 512
    int tid = threadIdx.x;
    int l = l0 + (tid & 127);
    int sub = tid >> 7;                    // split each chunk in 2
    int qs0 = (qz << 9) + (sub << 8);
    const __half* Pp = g_p + (size_t)nh * LL * LL;
    const float* rs = g_rs + nh * LL;
    float sum = 0.0f;
#pragma unroll 8
    for (int qq = 0; qq < 256; qq++) {
        int q = qs0 + qq;
        float pv = __half2float(__ldg(Pp + (size_t)q * LL + l));
        float rv = __ldg(rs + q);
        sum += (q >= l) ? pv * rv : 0.0f;
    }
    int slice = (qz << 1) + sub;           // 0..7
    g_part[((size_t)slice * NHTOT + nh) * LL + l] = sum;
}

// ---------------- K3b: reduce 8 partials ----------------------------------
__global__ void reduce2_kernel() {
    int idx = blockIdx.x * 256 + threadIdx.x;   // < NROW
    int nh = idx >> 11;
    int l = idx & (LL - 1);
    float sum = 0.0f;
#pragma unroll
    for (int sl = 0; sl < 8; sl++)
        sum += g_part[((size_t)sl * NHTOT + nh) * LL + l];
    g_cs[idx] = sum;
}

// ---------------- K4a: pre = diag*v + colsum*ov, back to [n][l][h*64+d] ----
__global__ void pre_kernel() {
    int idx = blockIdx.x * 256 + threadIdx.x;   // < NB*LL*DD
    int d = idx & 63;
    int h = (idx >> 6) & 15;
    int l = (idx >> 10) & (LL - 1);
    int n = idx >> 21;
    int r = ((n << 4) + h) * LL + l;
    size_t b = (size_t)r * DH + d;
    g_pre[idx] = g_dp[r] * g_v[b] + g_cs[r] * g_ov[b];
}

// ---------------- K4b: out = pre @ fc_w^T + fc_b ---------------------------
__global__ __launch_bounds__(256, 2) void fc_kernel(
        const float* __restrict__ Wfc, const float* __restrict__ bias,
        float* __restrict__ out) {
    extern __shared__ float4 sh[];
    float4* As = sh;
    float4* Bs = sh + 2048;
    int m0 = blockIdx.y << 7, o0 = blockIdx.x << 7;
    int tid = threadIdx.x;
    int ty = tid >> 4, tx = tid & 15;
    float acc[8][8];
#pragma unroll
    for (int i = 0; i < 8; i++)
#pragma unroll
        for (int j = 0; j < 8; j++) acc[i][j] = 0.0f;
    for (int k0 = 0; k0 < DD; k0 += 64) {
        __syncthreads();
        for (int it = tid; it < 2048; it += 256) {
            int row = it >> 4, e4 = it & 15;
            As[slot(row, e4)] =
                *(const float4*)(g_pre + (size_t)(m0 + row) * DD + k0 + (e4 << 2));
            Bs[slot(row, e4)] =
                *(const float4*)(Wfc + (size_t)(o0 + row) * DD + k0 + (e4 << 2));
        }
        __syncthreads();
        TILE_MMA(As, Bs, acc, tx, ty)
    }
#pragma unroll
    for (int i = 0; i < 8; i++) {
        int row = m0 + (ty << 3) + i;
#pragma unroll
        for (int j = 0; j < 8; j++) {
            int col = o0 + tx + (j << 4);
            out[(size_t)row * DD + col] = acc[i][j] + bias[col];
        }
    }
}

// ---------------- launch ----------------------------------------------------
extern "C" void kernel_launch(void* const* d_in, const int* in_sizes, int n_in,
                              void* d_out, int out_size) {
    const float* values = (const float*)d_in[0];
    const float* keys   = (const float*)d_in[1];
    const float* query  = (const float*)d_in[2];
    const float* ovals  = (const float*)d_in[3];
    const float* okeys  = (const float*)d_in[4];
    const float* Wv     = (const float*)d_in[5];
    const float* Wk     = (const float*)d_in[6];
    const float* Wq     = (const float*)d_in[7];
    const float* fcw    = (const float*)d_in[8];
    const float* fcb    = (const float*)d_in[9];
    float* out = (float*)d_out;

    float *pq, *pk, *pv, *pok, *pov;
    cudaGetSymbolAddress((void**)&pq,  g_q);
    cudaGetSymbolAddress((void**)&pk,  g_k);
    cudaGetSymbolAddress((void**)&pv,  g_v);
    cudaGetSymbolAddress((void**)&pok, g_ok);
    cudaGetSymbolAddress((void**)&pov, g_ov);

    cudaFuncSetAttribute(qk_kernel,
        cudaFuncAttributeMaxDynamicSharedMemorySize, 98304);
    cudaFuncSetAttribute(fc_kernel,
        cudaFuncAttributeMaxDynamicSharedMemorySize, 65536);

    proj2_kernel<<<512, 256>>>(query,  Wq, pq);
    proj2_kernel<<<512, 256>>>(keys,   Wk, pk);
    proj2_kernel<<<512, 256>>>(values, Wv, pv);
    proj2_kernel<<<512, 256>>>(okeys,  Wk, pok);
    proj2_kernel<<<512, 256>>>(ovals,  Wv, pov);
    diag_kernel<<<NROW / 8, 256>>>();
    qk_kernel<<<dim3(QTILES, NHTOT), 256, 98304>>>();
    colsum2_kernel<<<dim3(16, NHTOT, 4), 256>>>();
    reduce2_kernel<<<NROW / 256, 256>>>();
    pre_kernel<<<NB * LL * DD / 256, 256>>>();
    fc_kernel<<<dim3(DD / 128, NB * LL / 128), 256, 65536>>>(fcw, fcb, out);
}

// round 5
// speedup vs baseline: 3.4468x; 2.3484x over previous
#include <cuda_runtime.h>
#include <cuda_fp16.h>

// Problem constants
#define NB   2
#define LL   2048
#define DD   1024
#define DH   64
#define NHTOT 32            // NB*HH
#define NROW 65536          // NHTOT*LL
#define QTILES 16           // LL/128

// (1/sqrt(D)) * log2(e): energies pre-scaled into base-2 domain
#define CSCALE 0.04508422002778f

// ---------------- scratch (static device allocations; no cudaMalloc) -------
static __device__ float  g_q [NROW*DH];
static __device__ float  g_k [NROW*DH];
static __device__ float  g_v [NROW*DH];
static __device__ float  g_ok[NROW*DH];
static __device__ float  g_ov[NROW*DH];
static __device__ float  g_de[NROW];        // diag energies (unscaled)
static __device__ float  g_rs[NROW];        // 1 / row softmax denom
static __device__ float  g_dp[NROW];        // diag probability
static __device__ float  g_cs[NROW];        // column sums of off-diag probs
static __device__ float  g_part[8*NROW];    // per-qslice column partials
static __device__ float  g_pre[NB*LL*DD];   // pre-fc activations
static __device__ __half g_p[(size_t)NHTOT*LL*LL];  // unnormalized probs 2^e

// fast exp2, pure FFMA/ALU (avoids MUFU)
__device__ __forceinline__ float exp2c(float x) {
    x = fmaxf(x, -120.0f);
    float r = rintf(x);
    float f = x - r;                      // [-0.5, 0.5]
    float p = 0.0013333558f;
    p = fmaf(p, f, 0.0096181291f);
    p = fmaf(p, f, 0.0555041087f);
    p = fmaf(p, f, 0.2402265070f);
    p = fmaf(p, f, 0.6931471806f);
    p = fmaf(p, f, 1.0f);
    int ei = (int)r;
    float sc = __int_as_float((ei + 127) << 23);
    return p * sc;
}

__device__ __forceinline__ unsigned f2tf(float x) {
    unsigned r;
    asm("cvt.rna.tf32.f32 %0, %1;" : "=r"(r) : "f"(x));
    return r;
}

__device__ __forceinline__ void mma8(float c[4], const unsigned a[4],
                                     const unsigned b[2]) {
    asm volatile(
        "mma.sync.aligned.m16n8k8.row.col.f32.tf32.tf32.f32 "
        "{%0,%1,%2,%3}, {%4,%5,%6,%7}, {%8,%9}, {%0,%1,%2,%3};\n"
        : "+f"(c[0]), "+f"(c[1]), "+f"(c[2]), "+f"(c[3])
        : "r"(a[0]), "r"(a[1]), "r"(a[2]), "r"(a[3]), "r"(b[0]), "r"(b[1]));
}

// ---------------- K1: head-wise projection x @ W^T  (register-tiled) -------
__global__ __launch_bounds__(256) void proj2_kernel(
        const float* __restrict__ x, const float* __restrict__ W,
        float* __restrict__ out) {
    __shared__ __align__(16) float Wt[DH][68];    // Wt[e][d] = W[d][e]
    __shared__ __align__(16) float xst[DH][132];  // xst[e][row]
    int tid = threadIdx.x;
    for (int i = tid; i < DH * DH; i += 256) Wt[i & 63][i >> 6] = W[i];
    int r0 = blockIdx.x << 7;
    for (int i = tid; i < 2048; i += 256) {
        int row = i >> 4, e4 = i & 15;
        float4 v = *(const float4*)(x + (size_t)(r0 + row) * DH + (e4 << 2));
        xst[(e4 << 2) + 0][row] = v.x;
        xst[(e4 << 2) + 1][row] = v.y;
        xst[(e4 << 2) + 2][row] = v.z;
        xst[(e4 << 2) + 3][row] = v.w;
    }
    __syncthreads();
    int ty = tid >> 4, tx = tid & 15;
    int rr = ty << 3, cc = tx << 2;
    float acc[8][4];
#pragma unroll
    for (int i = 0; i < 8; i++)
#pragma unroll
        for (int j = 0; j < 4; j++) acc[i][j] = 0.0f;
#pragma unroll
    for (int e = 0; e < DH; e++) {
        float4 a0 = *(const float4*)&xst[e][rr];
        float4 a1 = *(const float4*)&xst[e][rr + 4];
        float4 b  = *(const float4*)&Wt[e][cc];
        float av[8] = {a0.x, a0.y, a0.z, a0.w, a1.x, a1.y, a1.z, a1.w};
#pragma unroll
        for (int i = 0; i < 8; i++) {
            acc[i][0] = fmaf(av[i], b.x, acc[i][0]);
            acc[i][1] = fmaf(av[i], b.y, acc[i][1]);
            acc[i][2] = fmaf(av[i], b.z, acc[i][2]);
            acc[i][3] = fmaf(av[i], b.w, acc[i][3]);
        }
    }
#pragma unroll
    for (int i = 0; i < 8; i++) {
        int row = r0 + rr + i;                 // (n, l, h) order
        int n = row >> 15;
        int l = (row >> 4) & (LL - 1);
        int h = row & 15;
        size_t orow = (size_t)((n << 4) + h) * LL + l;
        *(float4*)(out + orow * DH + cc) =
            make_float4(acc[i][0], acc[i][1], acc[i][2], acc[i][3]);
    }
}

// ---------------- K2a: diagonal energies q.k (one warp per row) ------------
__global__ void diag_kernel() {
    int g = blockIdx.x * 256 + threadIdx.x;
    int w = g >> 5, lane = g & 31;
    const float* qp = g_q + (size_t)w * DH;
    const float* kp = g_k + (size_t)w * DH;
    float a = qp[lane] * kp[lane] + qp[lane + 32] * kp[lane + 32];
#pragma unroll
    for (int o = 16; o; o >>= 1) a += __shfl_xor_sync(0xffffffffu, a, o);
    if (lane == 0) g_de[w] = a;
}

// ---------------- K2: tensor-core energies -> fp16 P + exact row sums ------
// Block: 256 threads = 8 warps in 2x4 grid; warp tile 64x32 of a 128x128 tile.
__global__ __launch_bounds__(256) void qk_tc_kernel() {
    extern __shared__ unsigned sh[];
    unsigned* qs = sh;                 // [128][68] tf32 q (scaled)
    unsigned* os = sh + 128 * 68;      // [128][68] tf32 ok; reused as ps/red
    int nh = blockIdx.y;
    int qt = (QTILES - 1) - blockIdx.x;   // heavy blocks first
    int q0 = qt << 7;
    const float* qb = g_q  + (size_t)nh * LL * DH;
    const float* ob = g_ok + (size_t)nh * LL * DH;
    __half* Pp = g_p + (size_t)nh * LL * LL;
    int tid = threadIdx.x;
    int lane = tid & 31, wid = tid >> 5;
    int wm = wid >> 2, wn = wid & 3;
    int gi = lane >> 2, qi = lane & 3;

    for (int i = tid; i < 2048; i += 256) {
        int row = i >> 4, c4 = (i & 15) << 2;
        float4 v = *(const float4*)(qb + (size_t)(q0 + row) * DH + c4);
        unsigned* d = qs + row * 68 + c4;
        d[0] = f2tf(v.x * CSCALE); d[1] = f2tf(v.y * CSCALE);
        d[2] = f2tf(v.z * CSCALE); d[3] = f2tf(v.w * CSCALE);
    }
    float s[8];
#pragma unroll
    for (int i = 0; i < 8; i++) s[i] = 0.0f;

    for (int l0 = 0; l0 <= q0; l0 += 128) {
        __syncthreads();
        for (int i = tid; i < 2048; i += 256) {
            int row = i >> 4, c4 = (i & 15) << 2;
            float4 v = *(const float4*)(ob + (size_t)(l0 + row) * DH + c4);
            unsigned* d = os + row * 68 + c4;
            d[0] = f2tf(v.x); d[1] = f2tf(v.y);
            d[2] = f2tf(v.z); d[3] = f2tf(v.w);
        }
        __syncthreads();
        float acc[4][4][4];
#pragma unroll
        for (int mt = 0; mt < 4; mt++)
#pragma unroll
            for (int nt = 0; nt < 4; nt++)
#pragma unroll
                for (int e = 0; e < 4; e++) acc[mt][nt][e] = 0.0f;
#pragma unroll
        for (int k0 = 0; k0 < DH; k0 += 8) {
            unsigned a[4][4], b[4][2];
#pragma unroll
            for (int mt = 0; mt < 4; mt++) {
                int rb = wm * 64 + mt * 16 + gi;
                a[mt][0] = qs[rb * 68 + k0 + qi];
                a[mt][1] = qs[(rb + 8) * 68 + k0 + qi];
                a[mt][2] = qs[rb * 68 + k0 + 4 + qi];
                a[mt][3] = qs[(rb + 8) * 68 + k0 + 4 + qi];
            }
#pragma unroll
            for (int nt = 0; nt < 4; nt++) {
                int nb = wn * 32 + nt * 8 + gi;
                b[nt][0] = os[nb * 68 + k0 + qi];
                b[nt][1] = os[nb * 68 + k0 + 4 + qi];
            }
#pragma unroll
            for (int mt = 0; mt < 4; mt++)
#pragma unroll
                for (int nt = 0; nt < 4; nt++)
                    mma8(acc[mt][nt], a[mt], b[nt]);
        }
        __syncthreads();               // all warps done reading os
        __half* ps = (__half*)os;      // [128][136] padded fp16 tile
        bool dt = (l0 == q0);
#pragma unroll
        for (int mt = 0; mt < 4; mt++) {
            int rl = wm * 64 + mt * 16 + gi;
#pragma unroll
            for (int nt = 0; nt < 4; nt++) {
                int cl = wn * 32 + nt * 8 + 2 * qi;
                float u0 = exp2c(acc[mt][nt][0]);
                float u1 = exp2c(acc[mt][nt][1]);
                float u2 = exp2c(acc[mt][nt][2]);
                float u3 = exp2c(acc[mt][nt][3]);
                if (dt) {   // causal + diagonal excluded (local coords, q0==l0)
                    if (cl     >= rl)     u0 = 0.0f;
                    if (cl + 1 >= rl)     u1 = 0.0f;
                    if (cl     >= rl + 8) u2 = 0.0f;
                    if (cl + 1 >= rl + 8) u3 = 0.0f;
                }
                s[mt * 2 + 0] += u0 + u1;
                s[mt * 2 + 1] += u2 + u3;
                *(__half2*)(ps + rl * 136 + cl)       = __floats2half2_rn(u0, u1);
                *(__half2*)(ps + (rl + 8) * 136 + cl) = __floats2half2_rn(u2, u3);
            }
        }
        __syncthreads();
        for (int i = tid; i < 2048; i += 256) {
            int row = i >> 4, c8 = (i & 15) << 3;
            *(float4*)(Pp + (size_t)(q0 + row) * LL + l0 + c8) =
                *(const float4*)(ps + row * 136 + c8);
        }
    }
    // final row-sum reduction: quad shuffle, then across the 4 warp columns
#pragma unroll
    for (int i = 0; i < 8; i++) {
        s[i] += __shfl_xor_sync(0xffffffffu, s[i], 1);
        s[i] += __shfl_xor_sync(0xffffffffu, s[i], 2);
    }
    __syncthreads();
    float* red = (float*)os;           // [128][4]
    if (qi == 0) {
#pragma unroll
        for (int mt = 0; mt < 4; mt++) {
            int rl = wm * 64 + mt * 16 + gi;
            red[rl * 4 + wn] = s[mt * 2 + 0];
            red[(rl + 8) * 4 + wn] = s[mt * 2 + 1];
        }
    }
    __syncthreads();
    if (tid < 128) {
        float tot = red[tid * 4] + red[tid * 4 + 1] +
                    red[tid * 4 + 2] + red[tid * 4 + 3];
        int row = nh * LL + q0 + tid;
        float ud = exp2c(g_de[row] * CSCALE);
        float rinv = 1.0f / (tot + ud);
        g_rs[row] = rinv;
        g_dp[row] = ud * rinv;
    }
}

// ---------------- K3: column partial sums (lower triangle only) ------------
__global__ void colsum2_kernel() {
    int nh = blockIdx.y;
    int l0 = blockIdx.x << 7;              // 16 column tiles of 128
    int qz = blockIdx.z;                   // 4 q-chunks of 512
    int tid = threadIdx.x;
    int l = l0 + (tid & 127);
    int sub = tid >> 7;                    // split each chunk in 2
    int qs0 = (qz << 9) + (sub << 8);
    const __half* Pp = g_p + (size_t)nh * LL * LL;
    const float* rs = g_rs + nh * LL;
    float sum = 0.0f;
    int qstart = (l > qs0) ? l : qs0;
#pragma unroll 8
    for (int q = qstart; q < qs0 + 256; q++) {
        float pv = __half2float(__ldg(Pp + (size_t)q * LL + l));
        sum += pv * __ldg(rs + q);
    }
    int slice = (qz << 1) + sub;           // 0..7
    g_part[((size_t)slice * NHTOT + nh) * LL + l] = sum;
}

// ---------------- K3b: reduce 8 partials ----------------------------------
__global__ void reduce2_kernel() {
    int idx = blockIdx.x * 256 + threadIdx.x;   // < NROW
    int nh = idx >> 11;
    int l = idx & (LL - 1);
    float sum = 0.0f;
#pragma unroll
    for (int sl = 0; sl < 8; sl++)
        sum += g_part[((size_t)sl * NHTOT + nh) * LL + l];
    g_cs[idx] = sum;
}

// ---------------- K4a: pre = diag*v + colsum*ov, back to [n][l][h*64+d] ----
__global__ void pre_kernel() {
    int idx = blockIdx.x * 256 + threadIdx.x;   // < NB*LL*DD
    int d = idx & 63;
    int h = (idx >> 6) & 15;
    int l = (idx >> 10) & (LL - 1);
    int n = idx >> 21;
    int r = ((n << 4) + h) * LL + l;
    size_t b = (size_t)r * DH + d;
    g_pre[idx] = g_dp[r] * g_v[b] + g_cs[r] * g_ov[b];
}

// ---------------- K4b: out = pre @ fc_w^T + fc_b (tensor core) -------------
__global__ __launch_bounds__(256) void fc_tc_kernel(
        const float* __restrict__ Wfc, const float* __restrict__ bias,
        float* __restrict__ out) {
    extern __shared__ unsigned sh[];
    unsigned* as_ = sh;            // [128][68]
    unsigned* bs_ = sh + 128 * 68; // [128][68]
    int m0 = blockIdx.y << 7, o0 = blockIdx.x << 7;
    int tid = threadIdx.x;
    int lane = tid & 31, wid = tid >> 5;
    int wm = wid >> 2, wn = wid & 3;
    int gi = lane >> 2, qi = lane & 3;
    float acc[4][4][4];
#pragma unroll
    for (int mt = 0; mt < 4; mt++)
#pragma unroll
        for (int nt = 0; nt < 4; nt++)
#pragma unroll
            for (int e = 0; e < 4; e++) acc[mt][nt][e] = 0.0f;
    for (int kg = 0; kg < DD; kg += 64) {
        __syncthreads();
        for (int i = tid; i < 2048; i += 256) {
            int row = i >> 4, c4 = (i & 15) << 2;
            float4 va = *(const float4*)(g_pre + (size_t)(m0 + row) * DD + kg + c4);
            unsigned* da = as_ + row * 68 + c4;
            da[0] = f2tf(va.x); da[1] = f2tf(va.y);
            da[2] = f2tf(va.z); da[3] = f2tf(va.w);
            float4 vb = *(const float4*)(Wfc + (size_t)(o0 + row) * DD + kg + c4);
            unsigned* db = bs_ + row * 68 + c4;
            db[0] = f2tf(vb.x); db[1] = f2tf(vb.y);
            db[2] = f2tf(vb.z); db[3] = f2tf(vb.w);
        }
        __syncthreads();
#pragma unroll
        for (int k0 = 0; k0 < 64; k0 += 8) {
            unsigned a[4][4], b[4][2];
#pragma unroll
            for (int mt = 0; mt < 4; mt++) {
                int rb = wm * 64 + mt * 16 + gi;
                a[mt][0] = as_[rb * 68 + k0 + qi];
                a[mt][1] = as_[(rb + 8) * 68 + k0 + qi];
                a[mt][2] = as_[rb * 68 + k0 + 4 + qi];
                a[mt][3] = as_[(rb + 8) * 68 + k0 + 4 + qi];
            }
#pragma unroll
            for (int nt = 0; nt < 4; nt++) {
                int nb = wn * 32 + nt * 8 + gi;
                b[nt][0] = bs_[nb * 68 + k0 + qi];
                b[nt][1] = bs_[nb * 68 + k0 + 4 + qi];
            }
#pragma unroll
            for (int mt = 0; mt < 4; mt++)
#pragma unroll
                for (int nt = 0; nt < 4; nt++)
                    mma8(acc[mt][nt], a[mt], b[nt]);
        }
    }
#pragma unroll
    for (int mt = 0; mt < 4; mt++) {
        int r0 = m0 + wm * 64 + mt * 16 + gi;
#pragma unroll
        for (int nt = 0; nt < 4; nt++) {
            int c0 = o0 + wn * 32 + nt * 8 + 2 * qi;
            float b0 = bias[c0], b1 = bias[c0 + 1];
            out[(size_t)r0 * DD + c0]           = acc[mt][nt][0] + b0;
            out[(size_t)r0 * DD + c0 + 1]       = acc[mt][nt][1] + b1;
            out[(size_t)(r0 + 8) * DD + c0]     = acc[mt][nt][2] + b0;
            out[(size_t)(r0 + 8) * DD + c0 + 1] = acc[mt][nt][3] + b1;
        }
    }
}

// ---------------- launch ----------------------------------------------------
extern "C" void kernel_launch(void* const* d_in, const int* in_sizes, int n_in,
                              void* d_out, int out_size) {
    const float* values = (const float*)d_in[0];
    const float* keys   = (const float*)d_in[1];
    const float* query  = (const float*)d_in[2];
    const float* ovals  = (const float*)d_in[3];
    const float* okeys  = (const float*)d_in[4];
    const float* Wv     = (const float*)d_in[5];
    const float* Wk     = (const float*)d_in[6];
    const float* Wq     = (const float*)d_in[7];
    const float* fcw    = (const float*)d_in[8];
    const float* fcb    = (const float*)d_in[9];
    float* out = (float*)d_out;

    float *pq, *pk, *pv, *pok, *pov;
    cudaGetSymbolAddress((void**)&pq,  g_q);
    cudaGetSymbolAddress((void**)&pk,  g_k);
    cudaGetSymbolAddress((void**)&pv,  g_v);
    cudaGetSymbolAddress((void**)&pok, g_ok);
    cudaGetSymbolAddress((void**)&pov, g_ov);

    const int SMEM = 2 * 128 * 68 * 4;   // 69632
    cudaFuncSetAttribute(qk_tc_kernel,
        cudaFuncAttributeMaxDynamicSharedMemorySize, SMEM);
    cudaFuncSetAttribute(fc_tc_kernel,
        cudaFuncAttributeMaxDynamicSharedMemorySize, SMEM);

    proj2_kernel<<<512, 256>>>(query,  Wq, pq);
    proj2_kernel<<<512, 256>>>(keys,   Wk, pk);
    proj2_kernel<<<512, 256>>>(values, Wv, pv);
    proj2_kernel<<<512, 256>>>(okeys,  Wk, pok);
    proj2_kernel<<<512, 256>>>(ovals,  Wv, pov);
    diag_kernel<<<NROW / 8, 256>>>();
    qk_tc_kernel<<<dim3(QTILES, NHTOT), 256, SMEM>>>();
    colsum2_kernel<<<dim3(16, NHTOT, 4), 256>>>();
    reduce2_kernel<<<NROW / 256, 256>>>();
    pre_kernel<<<NB * LL * DD / 256, 256>>>();
    fc_tc_kernel<<<dim3(DD / 128, NB * LL / 128), 256, SMEM>>>(fcw, fcb, out);
}

// round 6
// speedup vs baseline: 3.8390x; 1.1138x over previous
#include <cuda_runtime.h>
#include <cuda_fp16.h>

// Problem constants
#define NB   2
#define LL   2048
#define DD   1024
#define DH   64
#define NHTOT 32            // NB*HH
#define NROW 65536          // NHTOT*LL
#define QTILES 16           // LL/128

// (1/sqrt(D)) * log2(e): energies pre-scaled into base-2 domain
#define CSCALE 0.04508422002778f

// ---------------- scratch (static device allocations; no cudaMalloc) -------
static __device__ float  g_q [NROW*DH];     // tf32-rounded, pre-scaled by CSCALE
static __device__ float  g_k [NROW*DH];     // tf32-rounded
static __device__ float  g_v [NROW*DH];     // fp32 accurate
static __device__ float  g_ok[NROW*DH];     // tf32-rounded
static __device__ float  g_ov[NROW*DH];     // fp32 accurate
static __device__ float  g_de[NROW];        // diag energies (base-2 domain)
static __device__ float  g_rs[NROW];        // 1 / row softmax denom
static __device__ float  g_dp[NROW];        // diag probability
static __device__ float  g_cs[NROW];        // column sums of off-diag probs
static __device__ float  g_part[8*NROW];    // per-qslice column partials
static __device__ float  g_pre[NB*LL*DD];   // pre-fc activations (tf32-rounded)
static __device__ float  g_fcwt[DD*DD];     // fc weights (tf32-rounded)
static __device__ __half g_p[(size_t)NHTOT*LL*LL];  // unnormalized probs 2^e

// fast exp2, pure FFMA/ALU (avoids MUFU)
__device__ __forceinline__ float exp2c(float x) {
    x = fmaxf(x, -120.0f);
    float r = rintf(x);
    float f = x - r;                      // [-0.5, 0.5]
    float p = 0.0013333558f;
    p = fmaf(p, f, 0.0096181291f);
    p = fmaf(p, f, 0.0555041087f);
    p = fmaf(p, f, 0.2402265070f);
    p = fmaf(p, f, 0.6931471806f);
    p = fmaf(p, f, 1.0f);
    int ei = (int)r;
    float sc = __int_as_float((ei + 127) << 23);
    return p * sc;
}

__device__ __forceinline__ unsigned f2tf(float x) {
    unsigned r;
    asm("cvt.rna.tf32.f32 %0, %1;" : "=r"(r) : "f"(x));
    return r;
}

__device__ __forceinline__ void mma8(float c[4], const unsigned a[4],
                                     const unsigned b[2]) {
    asm volatile(
        "mma.sync.aligned.m16n8k8.row.col.f32.tf32.tf32.f32 "
        "{%0,%1,%2,%3}, {%4,%5,%6,%7}, {%8,%9}, {%0,%1,%2,%3};\n"
        : "+f"(c[0]), "+f"(c[1]), "+f"(c[2]), "+f"(c[3])
        : "r"(a[0]), "r"(a[1]), "r"(a[2]), "r"(a[3]), "r"(b[0]), "r"(b[1]));
}

// ---------------- K1: fused tensor-core projections ------------------------
// grid (512, 5): 128-row tile per block; sel picks tensor/weight/precision.
// 8 warps: wm = wid>>1 (32-row strips), wn = wid&1 (32-col strips).
__global__ __launch_bounds__(256) void proj_tc_kernel(
        const float* __restrict__ xq, const float* __restrict__ xk,
        const float* __restrict__ xv, const float* __restrict__ xok,
        const float* __restrict__ xov,
        const float* __restrict__ Wq, const float* __restrict__ Wk,
        const float* __restrict__ Wv) {
    extern __shared__ __align__(16) unsigned shm[];
    unsigned* xh = shm;                 // [128][68]
    unsigned* xl = shm + 128 * 68;      // [128][68] (split only)
    unsigned* Wh = xl + 128 * 68;       // [64][68]
    unsigned* Wl = Wh + 64 * 68;        // [64][68]
    int sel = blockIdx.y;
    const float* x; const float* W; float* out;
    bool split = (sel >= 3);
    switch (sel) {
        case 0: x = xq;  W = Wq; out = g_q;  break;
        case 1: x = xk;  W = Wk; out = g_k;  break;
        case 2: x = xok; W = Wk; out = g_ok; break;
        case 3: x = xv;  W = Wv; out = g_v;  break;
        default: x = xov; W = Wv; out = g_ov; break;
    }
    int tid = threadIdx.x;
    int r0 = blockIdx.x << 7;
    // W tile (64x64)
    for (int i = tid; i < 4096; i += 256) {
        int n = i >> 6, k = i & 63;
        float w = W[i];
        unsigned hi = f2tf(w);
        Wh[n * 68 + k] = hi;
        if (split) Wl[n * 68 + k] = f2tf(w - __uint_as_float(hi));
    }
    // x tile (128x64)
    for (int i = tid; i < 2048; i += 256) {
        int row = i >> 4, c4 = (i & 15) << 2;
        float4 v = *(const float4*)(x + (size_t)(r0 + row) * DH + c4);
        unsigned* d = xh + row * 68 + c4;
        unsigned h0 = f2tf(v.x), h1 = f2tf(v.y), h2 = f2tf(v.z), h3 = f2tf(v.w);
        d[0] = h0; d[1] = h1; d[2] = h2; d[3] = h3;
        if (split) {
            unsigned* dl = xl + row * 68 + c4;
            dl[0] = f2tf(v.x - __uint_as_float(h0));
            dl[1] = f2tf(v.y - __uint_as_float(h1));
            dl[2] = f2tf(v.z - __uint_as_float(h2));
            dl[3] = f2tf(v.w - __uint_as_float(h3));
        }
    }
    __syncthreads();
    int lane = tid & 31, wid = tid >> 5;
    int wm = wid >> 1, wn = wid & 1;
    int gi = lane >> 2, qi = lane & 3;
    float acc[2][4][4];
#pragma unroll
    for (int mt = 0; mt < 2; mt++)
#pragma unroll
        for (int nt = 0; nt < 4; nt++)
#pragma unroll
            for (int e = 0; e < 4; e++) acc[mt][nt][e] = 0.0f;
#pragma unroll
    for (int k0 = 0; k0 < DH; k0 += 8) {
        unsigned a[2][4], b[4][2];
#pragma unroll
        for (int mt = 0; mt < 2; mt++) {
            int rb = wm * 32 + mt * 16 + gi;
            a[mt][0] = xh[rb * 68 + k0 + qi];
            a[mt][1] = xh[(rb + 8) * 68 + k0 + qi];
            a[mt][2] = xh[rb * 68 + k0 + 4 + qi];
            a[mt][3] = xh[(rb + 8) * 68 + k0 + 4 + qi];
        }
#pragma unroll
        for (int nt = 0; nt < 4; nt++) {
            int nb = wn * 32 + nt * 8 + gi;
            b[nt][0] = Wh[nb * 68 + k0 + qi];
            b[nt][1] = Wh[nb * 68 + k0 + 4 + qi];
        }
#pragma unroll
        for (int mt = 0; mt < 2; mt++)
#pragma unroll
            for (int nt = 0; nt < 4; nt++)
                mma8(acc[mt][nt], a[mt], b[nt]);
        if (split) {
            unsigned al[2][4], bl[4][2];
#pragma unroll
            for (int mt = 0; mt < 2; mt++) {
                int rb = wm * 32 + mt * 16 + gi;
                al[mt][0] = xl[rb * 68 + k0 + qi];
                al[mt][1] = xl[(rb + 8) * 68 + k0 + qi];
                al[mt][2] = xl[rb * 68 + k0 + 4 + qi];
                al[mt][3] = xl[(rb + 8) * 68 + k0 + 4 + qi];
            }
#pragma unroll
            for (int nt = 0; nt < 4; nt++) {
                int nb = wn * 32 + nt * 8 + gi;
                bl[nt][0] = Wl[nb * 68 + k0 + qi];
                bl[nt][1] = Wl[nb * 68 + k0 + 4 + qi];
            }
#pragma unroll
            for (int mt = 0; mt < 2; mt++)
#pragma unroll
                for (int nt = 0; nt < 4; nt++) {
                    mma8(acc[mt][nt], a[mt], bl[nt]);
                    mma8(acc[mt][nt], al[mt], b[nt]);
                }
        }
    }
    float oscale = (sel == 0) ? CSCALE : 1.0f;
    bool rnd = (sel < 3);
#pragma unroll
    for (int mt = 0; mt < 2; mt++) {
#pragma unroll
        for (int half = 0; half < 2; half++) {
            int row = r0 + wm * 32 + mt * 16 + gi + half * 8;
            int n = row >> 15;
            int l = (row >> 4) & (LL - 1);
            int h = row & 15;
            size_t obase = ((size_t)((n << 4) + h) * LL + l) * DH;
#pragma unroll
            for (int nt = 0; nt < 4; nt++) {
                int c = wn * 32 + nt * 8 + 2 * qi;
                float v0 = acc[mt][nt][half * 2 + 0] * oscale;
                float v1 = acc[mt][nt][half * 2 + 1] * oscale;
                if (rnd) {
                    v0 = __uint_as_float(f2tf(v0));
                    v1 = __uint_as_float(f2tf(v1));
                }
                out[obase + c] = v0;
                out[obase + c + 1] = v1;
            }
        }
    }
}

// ---------------- K2a: diagonal energies q.k (one warp per row) ------------
// g_q is pre-scaled by CSCALE -> g_de is already in base-2 domain.
__global__ void diag_kernel() {
    int g = blockIdx.x * 256 + threadIdx.x;
    int w = g >> 5, lane = g & 31;
    const float* qp = g_q + (size_t)w * DH;
    const float* kp = g_k + (size_t)w * DH;
    float a = qp[lane] * kp[lane] + qp[lane + 32] * kp[lane + 32];
#pragma unroll
    for (int o = 16; o; o >>= 1) a += __shfl_xor_sync(0xffffffffu, a, o);
    if (lane == 0) g_de[w] = a;
}

// ---------------- K2: tensor-core energies -> fp16 P + exact row sums ------
__global__ __launch_bounds__(256) void qk_tc_kernel() {
    extern __shared__ unsigned sh[];
    unsigned* qs = sh;                 // [128][68] tf32 bits
    unsigned* os = sh + 128 * 68;      // [128][68]; reused as ps/red
    int nh = blockIdx.y;
    int qt = (QTILES - 1) - blockIdx.x;   // heavy blocks first
    int q0 = qt << 7;
    const unsigned* qb = (const unsigned*)g_q + (size_t)nh * LL * DH;
    const unsigned* ob = (const unsigned*)g_ok + (size_t)nh * LL * DH;
    __half* Pp = g_p + (size_t)nh * LL * LL;
    int tid = threadIdx.x;
    int lane = tid & 31, wid = tid >> 5;
    int wm = wid >> 2, wn = wid & 3;
    int gi = lane >> 2, qi = lane & 3;

    for (int i = tid; i < 2048; i += 256) {
        int row = i >> 4, c4 = (i & 15) << 2;
        *(uint4*)(qs + row * 68 + c4) =
            *(const uint4*)(qb + (size_t)(q0 + row) * DH + c4);
    }
    float s[8];
#pragma unroll
    for (int i = 0; i < 8; i++) s[i] = 0.0f;

    for (int l0 = 0; l0 <= q0; l0 += 128) {
        __syncthreads();
        for (int i = tid; i < 2048; i += 256) {
            int row = i >> 4, c4 = (i & 15) << 2;
            *(uint4*)(os + row * 68 + c4) =
                *(const uint4*)(ob + (size_t)(l0 + row) * DH + c4);
        }
        __syncthreads();
        float acc[4][4][4];
#pragma unroll
        for (int mt = 0; mt < 4; mt++)
#pragma unroll
            for (int nt = 0; nt < 4; nt++)
#pragma unroll
                for (int e = 0; e < 4; e++) acc[mt][nt][e] = 0.0f;
#pragma unroll
        for (int k0 = 0; k0 < DH; k0 += 8) {
            unsigned a[4][4], b[4][2];
#pragma unroll
            for (int mt = 0; mt < 4; mt++) {
                int rb = wm * 64 + mt * 16 + gi;
                a[mt][0] = qs[rb * 68 + k0 + qi];
                a[mt][1] = qs[(rb + 8) * 68 + k0 + qi];
                a[mt][2] = qs[rb * 68 + k0 + 4 + qi];
                a[mt][3] = qs[(rb + 8) * 68 + k0 + 4 + qi];
            }
#pragma unroll
            for (int nt = 0; nt < 4; nt++) {
                int nb = wn * 32 + nt * 8 + gi;
                b[nt][0] = os[nb * 68 + k0 + qi];
                b[nt][1] = os[nb * 68 + k0 + 4 + qi];
            }
#pragma unroll
            for (int mt = 0; mt < 4; mt++)
#pragma unroll
                for (int nt = 0; nt < 4; nt++)
                    mma8(acc[mt][nt], a[mt], b[nt]);
        }
        __syncthreads();               // all warps done reading os
        __half* ps = (__half*)os;      // [128][136] padded fp16 tile
        bool dt = (l0 == q0);
#pragma unroll
        for (int mt = 0; mt < 4; mt++) {
            int rl = wm * 64 + mt * 16 + gi;
#pragma unroll
            for (int nt = 0; nt < 4; nt++) {
                int cl = wn * 32 + nt * 8 + 2 * qi;
                float u0 = exp2c(acc[mt][nt][0]);
                float u1 = exp2c(acc[mt][nt][1]);
                float u2 = exp2c(acc[mt][nt][2]);
                float u3 = exp2c(acc[mt][nt][3]);
                if (dt) {   // causal + diagonal excluded (local coords)
                    if (cl     >= rl)     u0 = 0.0f;
                    if (cl + 1 >= rl)     u1 = 0.0f;
                    if (cl     >= rl + 8) u2 = 0.0f;
                    if (cl + 1 >= rl + 8) u3 = 0.0f;
                }
                s[mt * 2 + 0] += u0 + u1;
                s[mt * 2 + 1] += u2 + u3;
                *(__half2*)(ps + rl * 136 + cl)       = __floats2half2_rn(u0, u1);
                *(__half2*)(ps + (rl + 8) * 136 + cl) = __floats2half2_rn(u2, u3);
            }
        }
        __syncthreads();
        for (int i = tid; i < 2048; i += 256) {
            int row = i >> 4, c8 = (i & 15) << 3;
            *(float4*)(Pp + (size_t)(q0 + row) * LL + l0 + c8) =
                *(const float4*)(ps + row * 136 + c8);
        }
    }
#pragma unroll
    for (int i = 0; i < 8; i++) {
        s[i] += __shfl_xor_sync(0xffffffffu, s[i], 1);
        s[i] += __shfl_xor_sync(0xffffffffu, s[i], 2);
    }
    __syncthreads();
    float* red = (float*)os;           // [128][4]
    if (qi == 0) {
#pragma unroll
        for (int mt = 0; mt < 4; mt++) {
            int rl = wm * 64 + mt * 16 + gi;
            red[rl * 4 + wn] = s[mt * 2 + 0];
            red[(rl + 8) * 4 + wn] = s[mt * 2 + 1];
        }
    }
    __syncthreads();
    if (tid < 128) {
        float tot = red[tid * 4] + red[tid * 4 + 1] +
                    red[tid * 4 + 2] + red[tid * 4 + 3];
        int row = nh * LL + q0 + tid;
        float ud = exp2c(g_de[row]);       // already base-2 scaled
        float rinv = 1.0f / (tot + ud);
        g_rs[row] = rinv;
        g_dp[row] = ud * rinv;
    }
}

// ---------------- K3: column partial sums (lower triangle only) ------------
__global__ void colsum2_kernel() {
    int nh = blockIdx.y;
    int l0 = blockIdx.x << 7;              // 16 column tiles of 128
    int qz = blockIdx.z;                   // 4 q-chunks of 512
    int tid = threadIdx.x;
    int l = l0 + (tid & 127);
    int sub = tid >> 7;                    // split each chunk in 2
    int qs0 = (qz << 9) + (sub << 8);
    const __half* Pp = g_p + (size_t)nh * LL * LL;
    const float* rs = g_rs + nh * LL;
    float sum = 0.0f;
    int qstart = (l > qs0) ? l : qs0;
#pragma unroll 8
    for (int q = qstart; q < qs0 + 256; q++) {
        float pv = __half2float(__ldg(Pp + (size_t)q * LL + l));
        sum += pv * __ldg(rs + q);
    }
    int slice = (qz << 1) + sub;           // 0..7
    g_part[((size_t)slice * NHTOT + nh) * LL + l] = sum;
}

// ---------------- K3b: reduce 8 partials ----------------------------------
__global__ void reduce2_kernel() {
    int idx = blockIdx.x * 256 + threadIdx.x;   // < NROW
    int nh = idx >> 11;
    int l = idx & (LL - 1);
    float sum = 0.0f;
#pragma unroll
    for (int sl = 0; sl < 8; sl++)
        sum += g_part[((size_t)sl * NHTOT + nh) * LL + l];
    g_cs[idx] = sum;
}

// ---------------- K4a: pre = diag*v + colsum*ov (tf32-rounded) -------------
__global__ void pre_kernel() {
    int idx = blockIdx.x * 256 + threadIdx.x;   // < NB*LL*DD
    int d = idx & 63;
    int h = (idx >> 6) & 15;
    int l = (idx >> 10) & (LL - 1);
    int n = idx >> 21;
    int r = ((n << 4) + h) * LL + l;
    size_t b = (size_t)r * DH + d;
    float v = g_dp[r] * g_v[b] + g_cs[r] * g_ov[b];
    g_pre[idx] = __uint_as_float(f2tf(v));
}

// ---------------- K4a': fc weight -> tf32 bits ------------------------------
__global__ void wcvt_kernel(const float* __restrict__ w) {
    int i = blockIdx.x * 256 + threadIdx.x;
    g_fcwt[i] = __uint_as_float(f2tf(w[i]));
}

// ---------------- K4b: out = pre @ fc_w^T + fc_b (tensor core) -------------
__global__ __launch_bounds__(256) void fc_tc_kernel(
        const float* __restrict__ bias, float* __restrict__ out) {
    extern __shared__ unsigned sh[];
    unsigned* as_ = sh;            // [128][68]
    unsigned* bs_ = sh + 128 * 68; // [128][68]
    const unsigned* Ap = (const unsigned*)g_pre;
    const unsigned* Bp = (const unsigned*)g_fcwt;
    int m0 = blockIdx.y << 7, o0 = blockIdx.x << 7;
    int tid = threadIdx.x;
    int lane = tid & 31, wid = tid >> 5;
    int wm = wid >> 2, wn = wid & 3;
    int gi = lane >> 2, qi = lane & 3;
    float acc[4][4][4];
#pragma unroll
    for (int mt = 0; mt < 4; mt++)
#pragma unroll
        for (int nt = 0; nt < 4; nt++)
#pragma unroll
            for (int e = 0; e < 4; e++) acc[mt][nt][e] = 0.0f;
    for (int kg = 0; kg < DD; kg += 64) {
        __syncthreads();
        for (int i = tid; i < 2048; i += 256) {
            int row = i >> 4, c4 = (i & 15) << 2;
            *(uint4*)(as_ + row * 68 + c4) =
                *(const uint4*)(Ap + (size_t)(m0 + row) * DD + kg + c4);
            *(uint4*)(bs_ + row * 68 + c4) =
                *(const uint4*)(Bp + (size_t)(o0 + row) * DD + kg + c4);
        }
        __syncthreads();
#pragma unroll
        for (int k0 = 0; k0 < 64; k0 += 8) {
            unsigned a[4][4], b[4][2];
#pragma unroll
            for (int mt = 0; mt < 4; mt++) {
                int rb = wm * 64 + mt * 16 + gi;
                a[mt][0] = as_[rb * 68 + k0 + qi];
                a[mt][1] = as_[(rb + 8) * 68 + k0 + qi];
                a[mt][2] = as_[rb * 68 + k0 + 4 + qi];
                a[mt][3] = as_[(rb + 8) * 68 + k0 + 4 + qi];
            }
#pragma unroll
            for (int nt = 0; nt < 4; nt++) {
                int nb = wn * 32 + nt * 8 + gi;
                b[nt][0] = bs_[nb * 68 + k0 + qi];
                b[nt][1] = bs_[nb * 68 + k0 + 4 + qi];
            }
#pragma unroll
            for (int mt = 0; mt < 4; mt++)
#pragma unroll
                for (int nt = 0; nt < 4; nt++)
                    mma8(acc[mt][nt], a[mt], b[nt]);
        }
    }
#pragma unroll
    for (int mt = 0; mt < 4; mt++) {
        int r0 = m0 + wm * 64 + mt * 16 + gi;
#pragma unroll
        for (int nt = 0; nt < 4; nt++) {
            int c0 = o0 + wn * 32 + nt * 8 + 2 * qi;
            float b0 = bias[c0], b1 = bias[c0 + 1];
            out[(size_t)r0 * DD + c0]           = acc[mt][nt][0] + b0;
            out[(size_t)r0 * DD + c0 + 1]       = acc[mt][nt][1] + b1;
            out[(size_t)(r0 + 8) * DD + c0]     = acc[mt][nt][2] + b0;
            out[(size_t)(r0 + 8) * DD + c0 + 1] = acc[mt][nt][3] + b1;
        }
    }
}

// ---------------- launch ----------------------------------------------------
extern "C" void kernel_launch(void* const* d_in, const int* in_sizes, int n_in,
                              void* d_out, int out_size) {
    const float* values = (const float*)d_in[0];
    const float* keys   = (const float*)d_in[1];
    const float* query  = (const float*)d_in[2];
    const float* ovals  = (const float*)d_in[3];
    const float* okeys  = (const float*)d_in[4];
    const float* Wv     = (const float*)d_in[5];
    const float* Wk     = (const float*)d_in[6];
    const float* Wq     = (const float*)d_in[7];
    const float* fcw    = (const float*)d_in[8];
    const float* fcb    = (const float*)d_in[9];
    float* out = (float*)d_out;

    const int SMEM_QK = 2 * 128 * 68 * 4;                 // 69632
    const int SMEM_PJ = (2 * 128 + 2 * 64) * 68 * 4;      // 104448
    cudaFuncSetAttribute(proj_tc_kernel,
        cudaFuncAttributeMaxDynamicSharedMemorySize, SMEM_PJ);
    cudaFuncSetAttribute(qk_tc_kernel,
        cudaFuncAttributeMaxDynamicSharedMemorySize, SMEM_QK);
    cudaFuncSetAttribute(fc_tc_kernel,
        cudaFuncAttributeMaxDynamicSharedMemorySize, SMEM_QK);

    proj_tc_kernel<<<dim3(512, 5), 256, SMEM_PJ>>>(
        query, keys, values, okeys, ovals, Wq, Wk, Wv);
    wcvt_kernel<<<DD * DD / 256, 256>>>(fcw);
    diag_kernel<<<NROW / 8, 256>>>();
    qk_tc_kernel<<<dim3(QTILES, NHTOT), 256, SMEM_QK>>>();
    colsum2_kernel<<<dim3(16, NHTOT, 4), 256>>>();
    reduce2_kernel<<<NROW / 256, 256>>>();
    pre_kernel<<<NB * LL * DD / 256, 256>>>();
    fc_tc_kernel<<<dim3(DD / 128, NB * LL / 128), 256, SMEM_QK>>>(fcb, out);
}

// round 9
// speedup vs baseline: 4.0730x; 1.0610x over previous
#include <cuda_runtime.h>
#include <cuda_fp16.h>

// Problem constants
#define NB   2
#define LL   2048
#define DD   1024
#define DH   64
#define NHTOT 32            // NB*HH
#define NROW 65536          // NHTOT*LL
#define QTILES 16           // LL/128

// (1/sqrt(D)) * log2(e): energies pre-scaled into base-2 domain
#define CSCALE 0.04508422002778f

// ---------------- scratch (static device allocations; no cudaMalloc) -------
static __device__ float  g_q [NROW*DH];     // tf32-rounded, pre-scaled by CSCALE
static __device__ float  g_k [NROW*DH];     // tf32-rounded
static __device__ float  g_v [NROW*DH];     // fp32 accurate
static __device__ float  g_ok[NROW*DH];     // tf32-rounded
static __device__ float  g_ov[NROW*DH];     // fp32 accurate
static __device__ float  g_de[NROW];        // diag energies (base-2 domain)
static __device__ float  g_rs[NROW];        // 1 / row softmax denom
static __device__ float  g_dp[NROW];        // diag probability
static __device__ float  g_cs[NROW];        // column sums of off-diag probs
static __device__ float  g_part[8*NROW];    // per-qslice column partials
static __device__ float  g_pre[NB*LL*DD];   // pre-fc activations (tf32-rounded)
static __device__ float  g_fcwt[DD*DD];     // fc weights (tf32-rounded)
static __device__ __half g_p[(size_t)NHTOT*LL*LL];  // unnormalized probs 2^e

// MUFU.EX2 (fast exp2 on the MUFU pipe)
__device__ __forceinline__ float ex2(float x) {
    float r;
    asm("ex2.approx.ftz.f32 %0, %1;" : "=f"(r) : "f"(x));
    return r;
}

__device__ __forceinline__ unsigned f2tf(float x) {
    unsigned r;
    asm("cvt.rna.tf32.f32 %0, %1;" : "=r"(r) : "f"(x));
    return r;
}

__device__ __forceinline__ void mma8(float c[4], const unsigned a[4],
                                     const unsigned b[2]) {
    asm volatile(
        "mma.sync.aligned.m16n8k8.row.col.f32.tf32.tf32.f32 "
        "{%0,%1,%2,%3}, {%4,%5,%6,%7}, {%8,%9}, {%0,%1,%2,%3};\n"
        : "+f"(c[0]), "+f"(c[1]), "+f"(c[2]), "+f"(c[3])
        : "r"(a[0]), "r"(a[1]), "r"(a[2]), "r"(a[3]), "r"(b[0]), "r"(b[1]));
}

// ---------------- K1: fused tensor-core projections ------------------------
// grid (512, 5): 128-row tile per block; sel picks tensor/weight/precision.
__global__ __launch_bounds__(256) void proj_tc_kernel(
        const float* __restrict__ xq, const float* __restrict__ xk,
        const float* __restrict__ xv, const float* __restrict__ xok,
        const float* __restrict__ xov,
        const float* __restrict__ Wq, const float* __restrict__ Wk,
        const float* __restrict__ Wv) {
    extern __shared__ __align__(16) unsigned shm[];
    unsigned* xh = shm;                 // [128][68]
    unsigned* xl = shm + 128 * 68;      // [128][68] (split only)
    unsigned* Wh = xl + 128 * 68;       // [64][68]
    unsigned* Wl = Wh + 64 * 68;        // [64][68]
    int sel = blockIdx.y;
    const float* x; const float* W; float* out;
    bool split = (sel >= 3);
    switch (sel) {
        case 0: x = xq;  W = Wq; out = g_q;  break;
        case 1: x = xk;  W = Wk; out = g_k;  break;
        case 2: x = xok; W = Wk; out = g_ok; break;
        case 3: x = xv;  W = Wv; out = g_v;  break;
        default: x = xov; W = Wv; out = g_ov; break;
    }
    int tid = threadIdx.x;
    int r0 = blockIdx.x << 7;
    for (int i = tid; i < 4096; i += 256) {
        int n = i >> 6, k = i & 63;
        float w = W[i];
        unsigned hi = f2tf(w);
        Wh[n * 68 + k] = hi;
        if (split) Wl[n * 68 + k] = f2tf(w - __uint_as_float(hi));
    }
    for (int i = tid; i < 2048; i += 256) {
        int row = i >> 4, c4 = (i & 15) << 2;
        float4 v = *(const float4*)(x + (size_t)(r0 + row) * DH + c4);
        unsigned* d = xh + row * 68 + c4;
        unsigned h0 = f2tf(v.x), h1 = f2tf(v.y), h2 = f2tf(v.z), h3 = f2tf(v.w);
        d[0] = h0; d[1] = h1; d[2] = h2; d[3] = h3;
        if (split) {
            unsigned* dl = xl + row * 68 + c4;
            dl[0] = f2tf(v.x - __uint_as_float(h0));
            dl[1] = f2tf(v.y - __uint_as_float(h1));
            dl[2] = f2tf(v.z - __uint_as_float(h2));
            dl[3] = f2tf(v.w - __uint_as_float(h3));
        }
    }
    __syncthreads();
    int lane = tid & 31, wid = tid >> 5;
    int wm = wid >> 1, wn = wid & 1;
    int gi = lane >> 2, qi = lane & 3;
    float acc[2][4][4];
#pragma unroll
    for (int mt = 0; mt < 2; mt++)
#pragma unroll
        for (int nt = 0; nt < 4; nt++)
#pragma unroll
            for (int e = 0; e < 4; e++) acc[mt][nt][e] = 0.0f;
#pragma unroll
    for (int k0 = 0; k0 < DH; k0 += 8) {
        unsigned a[2][4], b[4][2];
#pragma unroll
        for (int mt = 0; mt < 2; mt++) {
            int rb = wm * 32 + mt * 16 + gi;
            a[mt][0] = xh[rb * 68 + k0 + qi];
            a[mt][1] = xh[(rb + 8) * 68 + k0 + qi];
            a[mt][2] = xh[rb * 68 + k0 + 4 + qi];
            a[mt][3] = xh[(rb + 8) * 68 + k0 + 4 + qi];
        }
#pragma unroll
        for (int nt = 0; nt < 4; nt++) {
            int nb = wn * 32 + nt * 8 + gi;
            b[nt][0] = Wh[nb * 68 + k0 + qi];
            b[nt][1] = Wh[nb * 68 + k0 + 4 + qi];
        }
#pragma unroll
        for (int mt = 0; mt < 2; mt++)
#pragma unroll
            for (int nt = 0; nt < 4; nt++)
                mma8(acc[mt][nt], a[mt], b[nt]);
        if (split) {
            unsigned al[2][4], bl[4][2];
#pragma unroll
            for (int mt = 0; mt < 2; mt++) {
                int rb = wm * 32 + mt * 16 + gi;
                al[mt][0] = xl[rb * 68 + k0 + qi];
                al[mt][1] = xl[(rb + 8) * 68 + k0 + qi];
                al[mt][2] = xl[rb * 68 + k0 + 4 + qi];
                al[mt][3] = xl[(rb + 8) * 68 + k0 + 4 + qi];
            }
#pragma unroll
            for (int nt = 0; nt < 4; nt++) {
                int nb = wn * 32 + nt * 8 + gi;
                bl[nt][0] = Wl[nb * 68 + k0 + qi];
                bl[nt][1] = Wl[nb * 68 + k0 + 4 + qi];
            }
#pragma unroll
            for (int mt = 0; mt < 2; mt++)
#pragma unroll
                for (int nt = 0; nt < 4; nt++) {
                    mma8(acc[mt][nt], a[mt], bl[nt]);
                    mma8(acc[mt][nt], al[mt], b[nt]);
                }
        }
    }
    float oscale = (sel == 0) ? CSCALE : 1.0f;
    bool rnd = (sel < 3);
#pragma unroll
    for (int mt = 0; mt < 2; mt++) {
#pragma unroll
        for (int half = 0; half < 2; half++) {
            int row = r0 + wm * 32 + mt * 16 + gi + half * 8;
            int n = row >> 15;
            int l = (row >> 4) & (LL - 1);
            int h = row & 15;
            size_t obase = ((size_t)((n << 4) + h) * LL + l) * DH;
#pragma unroll
            for (int nt = 0; nt < 4; nt++) {
                int c = wn * 32 + nt * 8 + 2 * qi;
                float v0 = acc[mt][nt][half * 2 + 0] * oscale;
                float v1 = acc[mt][nt][half * 2 + 1] * oscale;
                if (rnd) {
                    v0 = __uint_as_float(f2tf(v0));
                    v1 = __uint_as_float(f2tf(v1));
                }
                out[obase + c] = v0;
                out[obase + c + 1] = v1;
            }
        }
    }
}

// ---------------- K2a: diagonal energies q.k (one warp per row) ------------
__global__ void diag_kernel() {
    int g = blockIdx.x * 256 + threadIdx.x;
    int w = g >> 5, lane = g & 31;
    const float* qp = g_q + (size_t)w * DH;
    const float* kp = g_k + (size_t)w * DH;
    float a = qp[lane] * kp[lane] + qp[lane + 32] * kp[lane + 32];
#pragma unroll
    for (int o = 16; o; o >>= 1) a += __shfl_xor_sync(0xffffffffu, a, o);
    if (lane == 0) g_de[w] = a;
}

// ---------------- K2: tensor-core energies -> fp16 P + exact row sums ------
// MUFU.EX2 epilogue; separate fp16 staging buffer (one barrier fewer / tile).
__global__ __launch_bounds__(256) void qk_tc_kernel() {
    extern __shared__ unsigned sh[];
    unsigned* qs = sh;                  // [128][68] tf32 bits
    unsigned* os = sh + 128 * 68;       // [128][68]
    __half*  ps = (__half*)(sh + 2 * 128 * 68);  // [128][136]
    int nh = blockIdx.y;
    int qt = (QTILES - 1) - blockIdx.x;   // heavy blocks first
    int q0 = qt << 7;
    const unsigned* qb = (const unsigned*)g_q + (size_t)nh * LL * DH;
    const unsigned* ob = (const unsigned*)g_ok + (size_t)nh * LL * DH;
    __half* Pp = g_p + (size_t)nh * LL * LL;
    int tid = threadIdx.x;
    int lane = tid & 31, wid = tid >> 5;
    int wm = wid >> 2, wn = wid & 3;
    int gi = lane >> 2, qi = lane & 3;

    for (int i = tid; i < 2048; i += 256) {
        int row = i >> 4, c4 = (i & 15) << 2;
        *(uint4*)(qs + row * 68 + c4) =
            *(const uint4*)(qb + (size_t)(q0 + row) * DH + c4);
    }
    float s[8];
#pragma unroll
    for (int i = 0; i < 8; i++) s[i] = 0.0f;

    for (int l0 = 0; l0 <= q0; l0 += 128) {
        __syncthreads();
        for (int i = tid; i < 2048; i += 256) {
            int row = i >> 4, c4 = (i & 15) << 2;
            *(uint4*)(os + row * 68 + c4) =
                *(const uint4*)(ob + (size_t)(l0 + row) * DH + c4);
        }
        __syncthreads();
        float acc[4][4][4];
#pragma unroll
        for (int mt = 0; mt < 4; mt++)
#pragma unroll
            for (int nt = 0; nt < 4; nt++)
#pragma unroll
                for (int e = 0; e < 4; e++) acc[mt][nt][e] = 0.0f;
#pragma unroll
        for (int k0 = 0; k0 < DH; k0 += 8) {
            unsigned a[4][4], b[4][2];
#pragma unroll
            for (int mt = 0; mt < 4; mt++) {
                int rb = wm * 64 + mt * 16 + gi;
                a[mt][0] = qs[rb * 68 + k0 + qi];
                a[mt][1] = qs[(rb + 8) * 68 + k0 + qi];
                a[mt][2] = qs[rb * 68 + k0 + 4 + qi];
                a[mt][3] = qs[(rb + 8) * 68 + k0 + 4 + qi];
            }
#pragma unroll
            for (int nt = 0; nt < 4; nt++) {
                int nb = wn * 32 + nt * 8 + gi;
                b[nt][0] = os[nb * 68 + k0 + qi];
                b[nt][1] = os[nb * 68 + k0 + 4 + qi];
            }
#pragma unroll
            for (int mt = 0; mt < 4; mt++)
#pragma unroll
                for (int nt = 0; nt < 4; nt++)
                    mma8(acc[mt][nt], a[mt], b[nt]);
        }
        // epilogue: MUFU exp2, stage fp16 into ps (no barrier needed: own buf)
        bool dt = (l0 == q0);
#pragma unroll
        for (int mt = 0; mt < 4; mt++) {
            int rl = wm * 64 + mt * 16 + gi;
#pragma unroll
            for (int nt = 0; nt < 4; nt++) {
                int cl = wn * 32 + nt * 8 + 2 * qi;
                float u0 = ex2(acc[mt][nt][0]);
                float u1 = ex2(acc[mt][nt][1]);
                float u2 = ex2(acc[mt][nt][2]);
                float u3 = ex2(acc[mt][nt][3]);
                if (dt) {   // causal + diagonal excluded (local coords)
                    if (cl     >= rl)     u0 = 0.0f;
                    if (cl + 1 >= rl)     u1 = 0.0f;
                    if (cl     >= rl + 8) u2 = 0.0f;
                    if (cl + 1 >= rl + 8) u3 = 0.0f;
                }
                s[mt * 2 + 0] += u0 + u1;
                s[mt * 2 + 1] += u2 + u3;
                *(__half2*)(ps + rl * 136 + cl)       = __floats2half2_rn(u0, u1);
                *(__half2*)(ps + (rl + 8) * 136 + cl) = __floats2half2_rn(u2, u3);
            }
        }
        __syncthreads();
        for (int i = tid; i < 2048; i += 256) {
            int row = i >> 4, c8 = (i & 15) << 3;
            *(float4*)(Pp + (size_t)(q0 + row) * LL + l0 + c8) =
                *(const float4*)(ps + row * 136 + c8);
        }
    }
#pragma unroll
    for (int i = 0; i < 8; i++) {
        s[i] += __shfl_xor_sync(0xffffffffu, s[i], 1);
        s[i] += __shfl_xor_sync(0xffffffffu, s[i], 2);
    }
    __syncthreads();
    float* red = (float*)ps;           // [128][4]
    if (qi == 0) {
#pragma unroll
        for (int mt = 0; mt < 4; mt++) {
            int rl = wm * 64 + mt * 16 + gi;
            red[rl * 4 + wn] = s[mt * 2 + 0];
            red[(rl + 8) * 4 + wn] = s[mt * 2 + 1];
        }
    }
    __syncthreads();
    if (tid < 128) {
        float tot = red[tid * 4] + red[tid * 4 + 1] +
                    red[tid * 4 + 2] + red[tid * 4 + 3];
        int row = nh * LL + q0 + tid;
        float ud = ex2(g_de[row]);       // already base-2 scaled
        float rinv = 1.0f / (tot + ud);
        g_rs[row] = rinv;
        g_dp[row] = ud * rinv;
    }
}

// ---------------- K3: column partial sums (lower triangle only) ------------
__global__ void colsum2_kernel() {
    int nh = blockIdx.y;
    int l0 = blockIdx.x << 7;              // 16 column tiles of 128
    int qz = blockIdx.z;                   // 4 q-chunks of 512
    int tid = threadIdx.x;
    int l = l0 + (tid & 127);
    int sub = tid >> 7;                    // split each chunk in 2
    int qs0 = (qz << 9) + (sub << 8);
    const __half* Pp = g_p + (size_t)nh * LL * LL;
    const float* rs = g_rs + nh * LL;
    float sum = 0.0f;
    int qstart = (l > qs0) ? l : qs0;
#pragma unroll 8
    for (int q = qstart; q < qs0 + 256; q++) {
        float pv = __half2float(__ldg(Pp + (size_t)q * LL + l));
        sum += pv * __ldg(rs + q);
    }
    int slice = (qz << 1) + sub;           // 0..7
    g_part[((size_t)slice * NHTOT + nh) * LL + l] = sum;
}

// ---------------- K3b: reduce 8 partials ----------------------------------
__global__ void reduce2_kernel() {
    int idx = blockIdx.x * 256 + threadIdx.x;   // < NROW
    int nh = idx >> 11;
    int l = idx & (LL - 1);
    float sum = 0.0f;
#pragma unroll
    for (int sl = 0; sl < 8; sl++)
        sum += g_part[((size_t)sl * NHTOT + nh) * LL + l];
    g_cs[idx] = sum;
}

// ---------------- K4a: pre = diag*v + colsum*ov (tf32-rounded) -------------
__global__ void pre_kernel() {
    int idx = blockIdx.x * 256 + threadIdx.x;   // < NB*LL*DD
    int d = idx & 63;
    int h = (idx >> 6) & 15;
    int l = (idx >> 10) & (LL - 1);
    int n = idx >> 21;
    int r = ((n << 4) + h) * LL + l;
    size_t b = (size_t)r * DH + d;
    float v = g_dp[r] * g_v[b] + g_cs[r] * g_ov[b];
    g_pre[idx] = __uint_as_float(f2tf(v));
}

// ---------------- K4a': fc weight -> tf32 bits ------------------------------
__global__ void wcvt_kernel(const float* __restrict__ w) {
    int i = blockIdx.x * 256 + threadIdx.x;
    g_fcwt[i] = __uint_as_float(f2tf(w[i]));
}

// ---------------- K4b: out = pre @ fc_w^T + fc_b (tensor core) -------------
__global__ __launch_bounds__(256) void fc_tc_kernel(
        const float* __restrict__ bias, float* __restrict__ out) {
    extern __shared__ unsigned sh[];
    unsigned* as_ = sh;            // [128][68]
    unsigned* bs_ = sh + 128 * 68; // [128][68]
    const unsigned* Ap = (const unsigned*)g_pre;
    const unsigned* Bp = (const unsigned*)g_fcwt;
    int m0 = blockIdx.y << 7, o0 = blockIdx.x << 7;
    int tid = threadIdx.x;
    int lane = tid & 31, wid = tid >> 5;
    int wm = wid >> 2, wn = wid & 3;
    int gi = lane >> 2, qi = lane & 3;
    float acc[4][4][4];
#pragma unroll
    for (int mt = 0; mt < 4; mt++)
#pragma unroll
        for (int nt = 0; nt < 4; nt++)
#pragma unroll
            for (int e = 0; e < 4; e++) acc[mt][nt][e] = 0.0f;
    for (int kg = 0; kg < DD; kg += 64) {
        __syncthreads();
        for (int i = tid; i < 2048; i += 256) {
            int row = i >> 4, c4 = (i & 15) << 2;
            *(uint4*)(as_ + row * 68 + c4) =
                *(const uint4*)(Ap + (size_t)(m0 + row) * DD + kg + c4);
            *(uint4*)(bs_ + row * 68 + c4) =
                *(const uint4*)(Bp + (size_t)(o0 + row) * DD + kg + c4);
        }
        __syncthreads();
#pragma unroll
        for (int k0 = 0; k0 < 64; k0 += 8) {
            unsigned a[4][4], b[4][2];
#pragma unroll
            for (int mt = 0; mt < 4; mt++) {
                int rb = wm * 64 + mt * 16 + gi;
                a[mt][0] = as_[rb * 68 + k0 + qi];
                a[mt][1] = as_[(rb + 8) * 68 + k0 + qi];
                a[mt][2] = as_[rb * 68 + k0 + 4 + qi];
                a[mt][3] = as_[(rb + 8) * 68 + k0 + 4 + qi];
            }
#pragma unroll
            for (int nt = 0; nt < 4; nt++) {
                int nb = wn * 32 + nt * 8 + gi;
                b[nt][0] = bs_[nb * 68 + k0 + qi];
                b[nt][1] = bs_[nb * 68 + k0 + 4 + qi];
            }
#pragma unroll
            for (int mt = 0; mt < 4; mt++)
#pragma unroll
                for (int nt = 0; nt < 4; nt++)
                    mma8(acc[mt][nt], a[mt], b[nt]);
        }
    }
#pragma unroll
    for (int mt = 0; mt < 4; mt++) {
        int r0 = m0 + wm * 64 + mt * 16 + gi;
#pragma unroll
        for (int nt = 0; nt < 4; nt++) {
            int c0 = o0 + wn * 32 + nt * 8 + 2 * qi;
            float b0 = bias[c0], b1 = bias[c0 + 1];
            out[(size_t)r0 * DD + c0]           = acc[mt][nt][0] + b0;
            out[(size_t)r0 * DD + c0 + 1]       = acc[mt][nt][1] + b1;
            out[(size_t)(r0 + 8) * DD + c0]     = acc[mt][nt][2] + b0;
            out[(size_t)(r0 + 8) * DD + c0 + 1] = acc[mt][nt][3] + b1;
        }
    }
}

// ---------------- launch ----------------------------------------------------
extern "C" void kernel_launch(void* const* d_in, const int* in_sizes, int n_in,
                              void* d_out, int out_size) {
    const float* values = (const float*)d_in[0];
    const float* keys   = (const float*)d_in[1];
    const float* query  = (const float*)d_in[2];
    const float* ovals  = (const float*)d_in[3];
    const float* okeys  = (const float*)d_in[4];
    const float* Wv     = (const float*)d_in[5];
    const float* Wk     = (const float*)d_in[6];
    const float* Wq     = (const float*)d_in[7];
    const float* fcw    = (const float*)d_in[8];
    const float* fcb    = (const float*)d_in[9];
    float* out = (float*)d_out;

    const int SMEM_FC = 2 * 128 * 68 * 4;                 // 69632
    const int SMEM_QK = 2 * 128 * 68 * 4 + 128 * 136 * 2; // 104448
    const int SMEM_PJ = (2 * 128 + 2 * 64) * 68 * 4;      // 104448
    cudaFuncSetAttribute(proj_tc_kernel,
        cudaFuncAttributeMaxDynamicSharedMemorySize, SMEM_PJ);
    cudaFuncSetAttribute(qk_tc_kernel,
        cudaFuncAttributeMaxDynamicSharedMemorySize, SMEM_QK);
    cudaFuncSetAttribute(fc_tc_kernel,
        cudaFuncAttributeMaxDynamicSharedMemorySize, SMEM_FC);

    proj_tc_kernel<<<dim3(512, 5), 256, SMEM_PJ>>>(
        query, keys, values, okeys, ovals, Wq, Wk, Wv);
    wcvt_kernel<<<DD * DD / 256, 256>>>(fcw);
    diag_kernel<<<NROW / 8, 256>>>();
    qk_tc_kernel<<<dim3(QTILES, NHTOT), 256, SMEM_QK>>>();
    colsum2_kernel<<<dim3(16, NHTOT, 4), 256>>>();
    reduce2_kernel<<<NROW / 256, 256>>>();
    pre_kernel<<<NB * LL * DD / 256, 256>>>();
    fc_tc_kernel<<<dim3(DD / 128, NB * LL / 128), 256, SMEM_FC>>>(fcb, out);
}